// round 5
// baseline (speedup 1.0000x reference)
#include <cuda_runtime.h>
#include <cstdint>
#include <math.h>

#define N_NODES 65536
#define C       256
#define B       8
#define EMB     512
#define NET     7
#define NNT     7
#define E_EDGES (N_NODES * 7)
#define NCOLS   (NET * C)      /* 1792 */
#define EPS     1e-5f

// ---------------- scratch (device globals; no allocs allowed) ----------------
__device__ float    g_h[(size_t)N_NODES * C];        // h1, then h3
__device__ float    g_h2[(size_t)N_NODES * C];       // conv1 out + emb
__device__ float    g_Y[(size_t)N_NODES * NCOLS];    // per-node per-type GEMM out (470 MB)
__device__ float    g_W[C * NCOLS];                  // tf32-converted core weights
__device__ float    g_TB[NET * NNT * C];             // one-hot bias table
__device__ float    g_S[B * C];
__device__ float    g_S2[B * C];
__device__ int      g_cnt[B];
__device__ float    g_mean[B * C];
__device__ float    g_istd[B * C];
__device__ float    g_emb[B * C];
__device__ int      g_deg[N_NODES];
__device__ int      g_fill[N_NODES];
__device__ int      g_rp[N_NODES];
__device__ int      g_bsum[256];
__device__ unsigned g_ct[E_EDGES];

// ---------------- helpers ----------------
__device__ __forceinline__ float to_tf32(float x) {
    float r;
    asm("cvt.rna.tf32.f32 %0, %1;" : "=f"(r) : "f"(x));
    return r;
}
__device__ __forceinline__ float silu(float z) {
    return z / (1.0f + expf(-z));
}
__device__ __forceinline__ void mma8(float* d, const float* a, const float* b) {
    asm volatile(
        "mma.sync.aligned.m16n8k8.row.col.f32.tf32.tf32.f32 "
        "{%0,%1,%2,%3}, {%4,%5,%6,%7}, {%8,%9}, {%0,%1,%2,%3};"
        : "+f"(d[0]), "+f"(d[1]), "+f"(d[2]), "+f"(d[3])
        : "r"(__float_as_uint(a[0])), "r"(__float_as_uint(a[1])),
          "r"(__float_as_uint(a[2])), "r"(__float_as_uint(a[3])),
          "r"(__float_as_uint(b[0])), "r"(__float_as_uint(b[1])));
}

// ---------------- zero kernels ----------------
__global__ void zero_f(float* p, int n) {
    int i = blockIdx.x * 256 + threadIdx.x;
    if (i < n) p[i] = 0.0f;
}
__global__ void zero_i(int* p, int n) {
    int i = blockIdx.x * 256 + threadIdx.x;
    if (i < n) p[i] = 0;
}

// ---------------- group norm ----------------
// 512 blocks x 256 threads; each block covers 128 contiguous nodes. batch_id is sorted,
// so we keep register accumulators and flush on graph change (<=8 flushes/block).
__global__ void gn_stats(const float* __restrict__ x, const int* __restrict__ bid,
                         float* S, float* S2, int* cnt) {
    const int c  = threadIdx.x;
    const int n0 = blockIdx.x * 128;
    float s = 0.0f, s2 = 0.0f;
    int curb = bid[n0];
    int lc = 0;
    for (int n = n0; n < n0 + 128; n++) {
        int b = bid[n];
        if (b != curb) {
            atomicAdd(&S[curb * C + c], s);
            atomicAdd(&S2[curb * C + c], s2);
            if (c == 0) atomicAdd(&cnt[curb], lc);
            s = 0.0f; s2 = 0.0f; lc = 0; curb = b;
        }
        float v = x[(size_t)n * C + c];
        s += v; s2 += v * v; lc++;
    }
    atomicAdd(&S[curb * C + c], s);
    atomicAdd(&S2[curb * C + c], s2);
    if (c == 0) atomicAdd(&cnt[curb], lc);
}

// grid = B, block = 256. cpg = 8, group of channel c = c/8.
__global__ void gn_finalize(const float* __restrict__ S, const float* __restrict__ S2,
                            const int* __restrict__ cnt,
                            float* meanA, float* istdA) {
    __shared__ float sS[C], sS2[C];
    const int c = threadIdx.x;
    const int b = blockIdx.x;
    sS[c]  = S[b * C + c];
    sS2[c] = S2[b * C + c];
    __syncthreads();
    const int g0 = (c >> 3) << 3;
    float Sg = 0.0f, S2g = 0.0f;
#pragma unroll
    for (int j = 0; j < 8; j++) { Sg += sS[g0 + j]; S2g += sS2[g0 + j]; }
    float count = (float)cnt[b] * 8.0f;
    float ic  = 1.0f / (count + EPS);
    float mu  = Sg * ic;
    float var = (S2g - 2.0f * mu * Sg + count * mu * mu) * ic;
    float istd = 1.0f / sqrtf(var + EPS);
    meanA[b * C + c] = mu;
    istdA[b * C + c] = istd;
}

// grid = N, block = 256: out = silu((x - mean)*istd*w + b)
__global__ void gn_norm_silu(const float* __restrict__ x, const int* __restrict__ bid,
                             const float* __restrict__ meanA, const float* __restrict__ istdA,
                             const float* __restrict__ w, const float* __restrict__ bb,
                             float* __restrict__ out) {
    const int i = blockIdx.x;
    const int c = threadIdx.x;
    const int b = bid[i];
    float v = x[(size_t)i * C + c];
    float z = (v - meanA[b * C + c]) * istdA[b * C + c] * w[c] + bb[c];
    out[(size_t)i * C + c] = silu(z);
}

// ---------------- weight restructure ----------------
// W[k*1792 + t*256 + o] = tf32(cw[(t*263+k)*256 + o])     (k < 256)
// TB[(t*7+nt)*256 + o]  = cw[(t*263+256+nt)*256 + o]
__global__ void build_w(const float* __restrict__ cw, float* __restrict__ W,
                        float* __restrict__ TB) {
    int idx = blockIdx.x * 256 + threadIdx.x;
    if (idx < C * NCOLS) {
        int k = idx / NCOLS;
        int r = idx % NCOLS;
        int t = r >> 8;
        int o = r & 255;
        W[idx] = to_tf32(cw[(size_t)(t * 263 + k) * C + o]);
    } else {
        int j = idx - C * NCOLS;
        if (j < NET * NNT * C) {
            int o  = j & 255;
            int tn = j >> 8;
            int nt = tn % 7;
            int t  = tn / 7;
            TB[j] = cw[(size_t)(t * 263 + 256 + nt) * C + o];
        }
    }
}

// ---------------- CSR build ----------------
__global__ void csr_deg(const int* __restrict__ ei, int* deg) {
    int e = blockIdx.x * 256 + threadIdx.x;
    if (e < E_EDGES) atomicAdd(&deg[ei[e]], 1);
}
__global__ void scan1(const int* __restrict__ deg, int* rp, int* bsum) {
    __shared__ int sm[256];
    int t = threadIdx.x;
    int i = blockIdx.x * 256 + t;
    int v = deg[i];
    sm[t] = v;
    __syncthreads();
    for (int off = 1; off < 256; off <<= 1) {
        int add = (t >= off) ? sm[t - off] : 0;
        __syncthreads();
        sm[t] += add;
        __syncthreads();
    }
    rp[i] = sm[t] - v;  // exclusive
    if (t == 255) bsum[blockIdx.x] = sm[255];
}
__global__ void scan2(int* bsum) {
    __shared__ int sm[256];
    int t = threadIdx.x;
    int v = bsum[t];
    sm[t] = v;
    __syncthreads();
    for (int off = 1; off < 256; off <<= 1) {
        int add = (t >= off) ? sm[t - off] : 0;
        __syncthreads();
        sm[t] += add;
        __syncthreads();
    }
    bsum[t] = sm[t] - v;  // exclusive
}
__global__ void scan3(int* rp, const int* __restrict__ bsum) {
    int i = blockIdx.x * 256 + threadIdx.x;
    rp[i] += bsum[blockIdx.x];
}
__global__ void csr_fill(const int* __restrict__ ei, const int* __restrict__ et,
                         const int* __restrict__ rp, int* fill, unsigned* ct) {
    int e = blockIdx.x * 256 + threadIdx.x;
    if (e < E_EDGES) {
        int row = ei[e];
        int col = ei[E_EDGES + e];
        int t   = et[e];
        int pos = rp[row] + atomicAdd(&fill[row], 1);
        ct[pos] = (unsigned)col | ((unsigned)t << 16);
    }
}

// ---------------- emb projection: silu(emb) @ emb_w + emb_b ----------------
__global__ void emb_proj(const float* __restrict__ emb, const float* __restrict__ ew,
                         const float* __restrict__ eb, float* __restrict__ out) {
    __shared__ float se[EMB];
    const int b = blockIdx.x;
    const int o = threadIdx.x;
    for (int k = o; k < EMB; k += 256) {
        float v = emb[b * EMB + k];
        se[k] = silu(v);
    }
    __syncthreads();
    float acc = eb[o];
#pragma unroll 8
    for (int k = 0; k < EMB; k++) acc += se[k] * ew[k * C + o];
    out[b * C + o] = acc;
}

// ---------------- GEMM: Y[N,1792] = A[N,256] @ W[256,1792] + TB[t][nt[row]] ----------------
#define BM 128
#define BN 128
#define BK 32
#define AS_ST 36
#define BS_ST 136

__global__ void __launch_bounds__(256, 2)
gemm_tf32(const float* __restrict__ A, const float* __restrict__ W,
          const float* __restrict__ TB, const int* __restrict__ ntype,
          float* __restrict__ Y) {
    __shared__ float As[BM * AS_ST];   // 18.4 KB, row-major [row][k]
    __shared__ float Bs[BK * BS_ST];   // 17.4 KB, [k][n]
    __shared__ float TBs[NNT * BN];    // 3.5 KB

    const int tid  = threadIdx.x;
    const int lane = tid & 31;
    const int warp = tid >> 5;
    const int wm = warp & 3;   // 4 warps along M (32 rows each)
    const int wn = warp >> 2;  // 2 warps along N (64 cols each)
    const int gID = lane >> 2;
    const int tig = lane & 3;

    const int rowBase = blockIdx.y * BM;
    const int nBase   = blockIdx.x * BN;
    const int tEdge   = nBase >> 8;  // 128 | 256 -> single edge-type per block

    // stage bias table slice for this block's 128 columns
    for (int idx = tid; idx < NNT * BN; idx += 256) {
        int nt = idx >> 7;
        int j  = idx & 127;
        TBs[idx] = TB[(tEdge * NNT + nt) * C + (nBase & 255) + j];
    }

    float acc[2][8][4];
#pragma unroll
    for (int a = 0; a < 2; a++)
#pragma unroll
        for (int b = 0; b < 8; b++)
#pragma unroll
            for (int c = 0; c < 4; c++) acc[a][b][c] = 0.0f;

    const int ar0 = tid >> 3;          // A: rows {ar0, +32, +64, +96}
    const int ac4 = (tid & 7) * 4;     //    cols c4..c4+3 of the 32-wide chunk
    const int bk0 = tid >> 5;          // B: k rows {bk0, +8, +16, +24}
    const int bc4 = (tid & 31) * 4;    //    cols c4..c4+3 of the 128-wide chunk

    for (int k0 = 0; k0 < C; k0 += BK) {
#pragma unroll
        for (int rr = 0; rr < 4; rr++) {
            int r = ar0 + rr * 32;
            float4 v = *(const float4*)&A[(size_t)(rowBase + r) * C + k0 + ac4];
            float4 w = make_float4(to_tf32(v.x), to_tf32(v.y), to_tf32(v.z), to_tf32(v.w));
            *(float4*)&As[r * AS_ST + ac4] = w;
        }
#pragma unroll
        for (int rr = 0; rr < 4; rr++) {
            int k = bk0 + rr * 8;
            float4 v = *(const float4*)&W[(size_t)(k0 + k) * NCOLS + nBase + bc4];
            *(float4*)&Bs[k * BS_ST + bc4] = v;
        }
        __syncthreads();

#pragma unroll
        for (int k8 = 0; k8 < BK; k8 += 8) {
            float afrag[2][4];
#pragma unroll
            for (int mf = 0; mf < 2; mf++) {
                int r = wm * 32 + mf * 16 + gID;
                afrag[mf][0] = As[r * AS_ST + k8 + tig];
                afrag[mf][1] = As[(r + 8) * AS_ST + k8 + tig];
                afrag[mf][2] = As[r * AS_ST + k8 + tig + 4];
                afrag[mf][3] = As[(r + 8) * AS_ST + k8 + tig + 4];
            }
            float bfrag[8][2];
#pragma unroll
            for (int nf = 0; nf < 8; nf++) {
                int cc = wn * 64 + nf * 8 + gID;
                bfrag[nf][0] = Bs[(k8 + tig) * BS_ST + cc];
                bfrag[nf][1] = Bs[(k8 + tig + 4) * BS_ST + cc];
            }
#pragma unroll
            for (int mf = 0; mf < 2; mf++)
#pragma unroll
                for (int nf = 0; nf < 8; nf++)
                    mma8(acc[mf][nf], afrag[mf], bfrag[nf]);
        }
        __syncthreads();
    }

    // epilogue: add one-hot bias table, store
#pragma unroll
    for (int mf = 0; mf < 2; mf++) {
        int rowLo = rowBase + wm * 32 + mf * 16 + gID;
        int rowHi = rowLo + 8;
        int ntLo = ntype[rowLo];
        int ntHi = ntype[rowHi];
#pragma unroll
        for (int nf = 0; nf < 8; nf++) {
            int colL = wn * 64 + nf * 8 + tig * 2;
            float2 lo = make_float2(acc[mf][nf][0] + TBs[ntLo * BN + colL],
                                    acc[mf][nf][1] + TBs[ntLo * BN + colL + 1]);
            float2 hi = make_float2(acc[mf][nf][2] + TBs[ntHi * BN + colL],
                                    acc[mf][nf][3] + TBs[ntHi * BN + colL + 1]);
            *(float2*)&Y[(size_t)rowLo * NCOLS + nBase + colL] = lo;
            *(float2*)&Y[(size_t)rowHi * NCOLS + nBase + colL] = hi;
        }
    }
}

// ---------------- gather: out[i,o] = add + sum_e Y[col_e, t_e*256+o] ----------------
// add_batch != nullptr: add_batch[bid[i]*256+o]; else add_node[i*256+o]
__global__ void gather_add(const float* __restrict__ Y, const int* __restrict__ rp,
                           const int* __restrict__ deg, const unsigned* __restrict__ ct,
                           const int* __restrict__ bid,
                           const float* __restrict__ add_batch,
                           const float* __restrict__ add_node,
                           float* __restrict__ out) {
    const int i = blockIdx.x;
    const int o = threadIdx.x;
    const int s = rp[i];
    const int d = deg[i];
    float acc;
    if (add_batch) acc = add_batch[bid[i] * C + o];
    else           acc = add_node[(size_t)i * C + o];
    for (int e = s; e < s + d; e++) {
        unsigned p = ct[e];
        int col = p & 0xFFFF;
        int t   = p >> 16;
        acc += Y[(size_t)col * NCOLS + t * C + o];
    }
    out[(size_t)i * C + o] = acc;
}

// ---------------- host ----------------
static inline float* devp_f(float* sym) { return sym; }

extern "C" void kernel_launch(void* const* d_in, const int* in_sizes, int n_in,
                              void* d_out, int out_size) {
    const float* x       = (const float*)d_in[0];
    const float* emb     = (const float*)d_in[1];
    const int*   bid     = (const int*)d_in[2];
    const int*   ei      = (const int*)d_in[3];   // [2,E]
    const int*   et      = (const int*)d_in[4];
    const int*   ntype   = (const int*)d_in[5];
    const float* gn1_w   = (const float*)d_in[6];
    const float* gn1_b   = (const float*)d_in[7];
    const float* conv1_w = (const float*)d_in[8];
    const float* emb_w   = (const float*)d_in[9];
    const float* emb_b   = (const float*)d_in[10];
    const float* gn2_w   = (const float*)d_in[11];
    const float* gn2_b   = (const float*)d_in[12];
    const float* conv2_w = (const float*)d_in[13];
    float* out = (float*)d_out;

    // resolve device-global addresses
    float *S, *S2, *meanA, *istdA, *h, *h2, *Y, *W, *TB, *embO;
    int *cnt, *deg, *fill, *rp, *bsum;
    unsigned* ct;
    cudaGetSymbolAddress((void**)&S,     g_S);
    cudaGetSymbolAddress((void**)&S2,    g_S2);
    cudaGetSymbolAddress((void**)&cnt,   g_cnt);
    cudaGetSymbolAddress((void**)&meanA, g_mean);
    cudaGetSymbolAddress((void**)&istdA, g_istd);
    cudaGetSymbolAddress((void**)&h,     g_h);
    cudaGetSymbolAddress((void**)&h2,    g_h2);
    cudaGetSymbolAddress((void**)&Y,     g_Y);
    cudaGetSymbolAddress((void**)&W,     g_W);
    cudaGetSymbolAddress((void**)&TB,    g_TB);
    cudaGetSymbolAddress((void**)&embO,  g_emb);
    cudaGetSymbolAddress((void**)&deg,   g_deg);
    cudaGetSymbolAddress((void**)&fill,  g_fill);
    cudaGetSymbolAddress((void**)&rp,    g_rp);
    cudaGetSymbolAddress((void**)&bsum,  g_bsum);
    cudaGetSymbolAddress((void**)&ct,    g_ct);

    dim3 gemmGrid(NCOLS / BN, N_NODES / BM);  // (14, 512)

    // --- zero per-call state ---
    zero_f<<<(B * C + 255) / 256, 256>>>(S, B * C);
    zero_f<<<(B * C + 255) / 256, 256>>>(S2, B * C);
    zero_i<<<1, 256>>>(cnt, B);
    zero_i<<<N_NODES / 256, 256>>>(deg, N_NODES);
    zero_i<<<N_NODES / 256, 256>>>(fill, N_NODES);

    // --- CSR (independent of data path) ---
    csr_deg<<<E_EDGES / 256, 256>>>(ei, deg);
    scan1<<<256, 256>>>(deg, rp, bsum);
    scan2<<<1, 256>>>(bsum);
    scan3<<<256, 256>>>(rp, bsum);
    csr_fill<<<E_EDGES / 256, 256>>>(ei, et, rp, fill, ct);

    // --- GN1 + silu ---
    gn_stats<<<512, 256>>>(x, bid, S, S2, cnt);
    gn_finalize<<<B, 256>>>(S, S2, cnt, meanA, istdA);
    gn_norm_silu<<<N_NODES, 256>>>(x, bid, meanA, istdA, gn1_w, gn1_b, h);

    // --- conv1 ---
    build_w<<<1841, 256>>>(conv1_w, W, TB);
    emb_proj<<<B, 256>>>(emb, emb_w, emb_b, embO);
    gemm_tf32<<<gemmGrid, 256>>>(h, W, TB, ntype, Y);
    gather_add<<<N_NODES, 256>>>(Y, rp, deg, ct, bid, embO, nullptr, h2);

    // --- GN2 + silu ---
    zero_f<<<(B * C + 255) / 256, 256>>>(S, B * C);
    zero_f<<<(B * C + 255) / 256, 256>>>(S2, B * C);
    zero_i<<<1, 256>>>(cnt, B);
    gn_stats<<<512, 256>>>(h2, bid, S, S2, cnt);
    gn_finalize<<<B, 256>>>(S, S2, cnt, meanA, istdA);
    gn_norm_silu<<<N_NODES, 256>>>(h2, bid, meanA, istdA, gn2_w, gn2_b, h);

    // --- conv2 + residual ---
    build_w<<<1841, 256>>>(conv2_w, W, TB);
    gemm_tf32<<<gemmGrid, 256>>>(h, W, TB, ntype, Y);
    gather_add<<<N_NODES, 256>>>(Y, rp, deg, ct, bid, nullptr, x, out);

    (void)in_sizes; (void)n_in; (void)out_size;
}